// round 7
// baseline (speedup 1.0000x reference)
#include <cuda_runtime.h>
#include <cuda_bf16.h>
#include <math.h>

#define T_SEQ   512
#define GATES   500
#define HID     125
#define DHID    250      // 2*HID
#define MLPH    512
#define NN      512

// Scratch (device globals; no allocation allowed)
__device__ float g_A[2 * T_SEQ * GATES];   // input projections (fwd/bwd)
__device__ float g_H[T_SEQ * DHID];        // concat hidden states
__device__ float g_P[2 * NN * MLPH];       // Pa, Pb(+b1)

// ---------------------------------------------------------------------------
// helpers
// ---------------------------------------------------------------------------
typedef unsigned long long ull;

__device__ __forceinline__ ull ffma2u(ull a, ull b, ull c) {
    ull d;
    asm("fma.rn.f32x2 %0, %1, %2, %3;" : "=l"(d) : "l"(a), "l"(b), "l"(c));
    return d;
}
__device__ __forceinline__ ull fadd2u(ull a, ull b) {
    ull d;
    asm("add.rn.f32x2 %0, %1, %2;" : "=l"(d) : "l"(a), "l"(b));
    return d;
}
__device__ __forceinline__ float2 u2f2(ull v) {
    float2 r;
    asm("mov.b64 {%0, %1}, %2;" : "=f"(r.x), "=f"(r.y) : "l"(v));
    return r;
}
__device__ __forceinline__ float tanh_mufu(float x) {
    float y;
    asm("tanh.approx.f32 %0, %1;" : "=f"(y) : "f"(x));
    return y;
}
__device__ __forceinline__ float sig_mufu(float x) {
    return 0.5f * tanh_mufu(0.5f * x) + 0.5f;
}

// no-op kernels to keep the ncu capture slot on lstm_kernel
__device__ int g_sink;
__global__ void nudge_kernel() {
    if (threadIdx.x > 4096) g_sink = 1;   // never taken
}

// ---------------------------------------------------------------------------
// Input projection, both directions in one launch.
// ---------------------------------------------------------------------------
__global__ void __launch_bounds__(256) proj_kernel(
    const float* __restrict__ x,
    const float* __restrict__ Wih_f, const float* __restrict__ bih_f,
    const float* __restrict__ bhh_f,
    const float* __restrict__ Wih_b, const float* __restrict__ bih_b,
    const float* __restrict__ bhh_b,
    float* __restrict__ Aout)
{
    const int dir = blockIdx.z;
    const float* __restrict__ W  = dir ? Wih_b : Wih_f;
    const float* __restrict__ bi = dir ? bih_b : bih_f;
    const float* __restrict__ bh = dir ? bhh_b : bhh_f;
    float* __restrict__ C = Aout + dir * (T_SEQ * GATES);

    __shared__ float As[16][34];
    __shared__ float Bs[16][34];

    const int tid = threadIdx.x;
    const int ti = tid & 15;
    const int tn = tid >> 4;
    const int m0 = blockIdx.x * 32;
    const int n0 = blockIdx.y * 32;

    float acc00 = 0.f, acc01 = 0.f, acc10 = 0.f, acc11 = 0.f;

    for (int kc = 0; kc < 125; kc += 16) {
#pragma unroll
        for (int it = 0; it < 2; ++it) {
            int idx = tid + it * 256;
            int mm = idx >> 4, kk = idx & 15;
            int k = kc + kk;
            int m = m0 + mm;
            int ra = dir ? (T_SEQ - 1 - m) : m;
            As[kk][mm] = (k < 125) ? x[(long)ra * 125 + k] : 0.f;
            int n = n0 + mm;
            Bs[kk][mm] = (n < GATES && k < 125) ? W[(long)n * 125 + k] : 0.f;
        }
        __syncthreads();
#pragma unroll
        for (int kk = 0; kk < 16; ++kk) {
            float2 av = *(const float2*)&As[kk][2 * ti];
            float2 bv = *(const float2*)&Bs[kk][2 * tn];
            acc00 = fmaf(av.x, bv.x, acc00);
            acc01 = fmaf(av.x, bv.y, acc01);
            acc10 = fmaf(av.y, bv.x, acc10);
            acc11 = fmaf(av.y, bv.y, acc11);
        }
        __syncthreads();
    }

    int m_ = m0 + 2 * ti;
    int n_ = n0 + 2 * tn;
    float b0 = 0.f, b1v = 0.f;
    if (n_ < GATES)     b0  = bi[n_] + bh[n_];
    if (n_ + 1 < GATES) b1v = bi[n_ + 1] + bh[n_ + 1];
    if (n_ < GATES) {
        C[(long)m_ * GATES + n_]       = acc00 + b0;
        C[(long)(m_ + 1) * GATES + n_] = acc10 + b0;
    }
    if (n_ + 1 < GATES) {
        C[(long)m_ * GATES + n_ + 1]       = acc01 + b1v;
        C[(long)(m_ + 1) * GATES + n_ + 1] = acc11 + b1v;
    }
}

// ---------------------------------------------------------------------------
// Pa / Pb in one launch. grid (16,16,2), block 256.
// ---------------------------------------------------------------------------
__global__ void __launch_bounds__(256) pab_kernel(
    const float* __restrict__ H,
    const float* __restrict__ W1,
    const float* __restrict__ b1,
    float* __restrict__ P)
{
    const int z = blockIdx.z;
    const float* __restrict__ B = W1 + (z ? DHID : 0);
    float* __restrict__ C = P + (long)z * NN * MLPH;

    __shared__ float As[16][34];
    __shared__ float Bs[16][34];

    const int tid = threadIdx.x;
    const int ti = tid & 15;
    const int tn = tid >> 4;
    const int m0 = blockIdx.x * 32;
    const int n0 = blockIdx.y * 32;

    float acc00 = 0.f, acc01 = 0.f, acc10 = 0.f, acc11 = 0.f;

    for (int kc = 0; kc < DHID; kc += 16) {
#pragma unroll
        for (int it = 0; it < 2; ++it) {
            int idx = tid + it * 256;
            int mm = idx >> 4, kk = idx & 15;
            int k = kc + kk;
            As[kk][mm] = (k < DHID) ? H[(long)(m0 + mm) * DHID + k] : 0.f;
            Bs[kk][mm] = (k < DHID) ? B[(long)(n0 + mm) * 500 + k] : 0.f;
        }
        __syncthreads();
#pragma unroll
        for (int kk = 0; kk < 16; ++kk) {
            float2 av = *(const float2*)&As[kk][2 * ti];
            float2 bv = *(const float2*)&Bs[kk][2 * tn];
            acc00 = fmaf(av.x, bv.x, acc00);
            acc01 = fmaf(av.x, bv.y, acc01);
            acc10 = fmaf(av.y, bv.x, acc10);
            acc11 = fmaf(av.y, bv.y, acc11);
        }
        __syncthreads();
    }

    int m_ = m0 + 2 * ti;
    int n_ = n0 + 2 * tn;
    float b0 = 0.f, b1v = 0.f;
    if (z) { b0 = b1[n_]; b1v = b1[n_ + 1]; }
    C[(long)m_ * MLPH + n_]           = acc00 + b0;
    C[(long)m_ * MLPH + n_ + 1]       = acc01 + b1v;
    C[(long)(m_ + 1) * MLPH + n_]     = acc10 + b0;
    C[(long)(m_ + 1) * MLPH + n_ + 1] = acc11 + b1v;
}

// ---------------------------------------------------------------------------
// LSTM recurrence, 2 rows per thread. grid = 2 (dir), block = 256.
// Thread t: u = t & 127 (active u < 125), half = t >> 7.
//   half 0 -> rows rA = u       (i-gate),  rB = 250 + u (g-gate)
//   half 1 -> rows rA = 125 + u (f-gate),  rB = 375 + u (o-gate)
// Weights: cols 0..87 of both rows in fp32 registers (88 ull),
//          cols 88..127 fp32 float4 in dynamic smem (cols >=125 zero).
// Update: half0 writes i*g to smem; half1 owns c: c = f*c + ig; h = o*tanh(c).
// Dynamic smem (floats):
//   [0, 20000)      : float4 weights [q 0..9][row 0..499]   (80KB)
//   [20000, 20128)  : i*g products
//   [20128, 20256)  : h (125 used, pad 0)
// ---------------------------------------------------------------------------
#define LSTM_SMEM_FLOATS (10 * 500 * 4 + 128 + 128)
#define LSTM_SMEM_BYTES  (LSTM_SMEM_FLOATS * 4)

__global__ void __launch_bounds__(256, 1) lstm_kernel(
    const float* __restrict__ Whh_f,
    const float* __restrict__ Whh_b,
    const float* __restrict__ A,     // [2][512][500]
    float* __restrict__ H)           // [512][250]
{
    extern __shared__ __align__(16) float dsm[];
    float* sh_wf = dsm;                  // 10*500 float4 = 20000 floats
    float* sh_ig = dsm + 20000;          // 128
    float* sh_h  = dsm + 20128;          // 128

    const int tid = threadIdx.x;
    const int dir = blockIdx.x;
    const float* __restrict__ Whh = dir ? Whh_b : Whh_f;
    const float* __restrict__ Ad = A + dir * (T_SEQ * GATES);

    const int u    = tid & 127;
    const int half = tid >> 7;
    const bool act = (u < HID);
    const int rA = half * 125 + u;          // i or f row
    const int rB = 250 + half * 125 + u;    // g or o row

    // stage fp32 smem weights: cols 88..127 (>=125 zero), layout [q][row]
    for (int idx = tid; idx < 10 * 500; idx += 256) {
        int q = idx / 500, rr = idx - q * 500;
        const float* w = Whh + rr * 125;
        float4 v;
        int c = 88 + 4 * q;
        v.x = (c + 0 < 125) ? w[c + 0] : 0.f;
        v.y = (c + 1 < 125) ? w[c + 1] : 0.f;
        v.z = (c + 2 < 125) ? w[c + 2] : 0.f;
        v.w = (c + 3 < 125) ? w[c + 3] : 0.f;
        ((float4*)sh_wf)[q * 500 + rr] = v;
    }

    // register weights: cols 0..87 of both rows, packed ull
    ull wA[44], wB[44];
    if (act) {
        const float* fA = Whh + rA * 125;
        const float* fB = Whh + rB * 125;
#pragma unroll
        for (int p = 0; p < 44; ++p) {
            float2 tA = make_float2(fA[2 * p], fA[2 * p + 1]);
            float2 tB = make_float2(fB[2 * p], fB[2 * p + 1]);
            wA[p] = *(ull*)&tA;
            wB[p] = *(ull*)&tB;
        }
    }

    if (tid < 128) sh_h[tid] = 0.f;   // includes pad slots
    float creg = 0.f;
    float aA = act ? Ad[rA] : 0.f;
    float aB = act ? Ad[rB] : 0.f;
    __syncthreads();

    const ulonglong2* h2  = (const ulonglong2*)sh_h;   // 32 granules of 16B
    const ulonglong2* wq2 = (const ulonglong2*)sh_wf;  // weight granules

    for (int t = 0; t < T_SEQ; ++t) {
        const bool has_next = (t < T_SEQ - 1);
        float aA_n = (act && has_next) ? Ad[(t + 1) * GATES + rA] : 0.f;
        float aB_n = (act && has_next) ? Ad[(t + 1) * GATES + rB] : 0.f;

        float fo_f = 0.f, fo_o = 0.f;   // half1's f and o
        if (act) {
            ull accA0 = 0ull, accA1 = 0ull, accB0 = 0ull, accB1 = 0ull;
#pragma unroll
            for (int p = 0; p < 22; ++p) {     // cols 0..87 (registers)
                ulonglong2 hv = h2[p];
                accA0 = ffma2u(wA[2 * p],     hv.x, accA0);
                accA1 = ffma2u(wA[2 * p + 1], hv.y, accA1);
                accB0 = ffma2u(wB[2 * p],     hv.x, accB0);
                accB1 = ffma2u(wB[2 * p + 1], hv.y, accB1);
            }
#pragma unroll
            for (int q = 0; q < 10; ++q) {     // cols 88..127 (fp32 smem)
                ulonglong2 hv = h2[22 + q];
                ulonglong2 wa = wq2[q * 500 + rA];
                ulonglong2 wb = wq2[q * 500 + rB];
                accA0 = ffma2u(wa.x, hv.x, accA0);
                accA1 = ffma2u(wa.y, hv.y, accA1);
                accB0 = ffma2u(wb.x, hv.x, accB0);
                accB1 = ffma2u(wb.y, hv.y, accB1);
            }
            float2 fa = u2f2(fadd2u(accA0, accA1));
            float2 fb = u2f2(fadd2u(accB0, accB1));
            float sA = fa.x + fa.y + aA;
            float sB = fb.x + fb.y + aB;
            float actA = sig_mufu(sA);                        // i or f
            float actB = half ? sig_mufu(sB) : tanh_mufu(sB); // o or g
            if (half == 0) {
                sh_ig[u] = actA * actB;    // i*g
            } else {
                fo_f = actA; fo_o = actB;
            }
        }
        __syncthreads();
        if (act && half == 1) {
            creg = fo_f * creg + sh_ig[u];
            float hv = fo_o * tanh_mufu(creg);
            sh_h[u] = hv;
            int row = dir ? (T_SEQ - 1 - t) : t;
            H[row * DHID + dir * HID + u] = hv;
        }
        __syncthreads();
        aA = aA_n; aB = aB_n;
    }
}

// ---------------------------------------------------------------------------
// Pairwise MLP contraction:
//   out[j][i] = b2 + sum_k W2[k] * tanh(Pa[i][k] + Pb[j][k])
// ---------------------------------------------------------------------------
__global__ void __launch_bounds__(256) pair_kernel(
    const float* __restrict__ Pa,   // [512][512]
    const float* __restrict__ Pb,   // [512][512] (b1 folded in)
    const float* __restrict__ W2,   // [512]
    const float* __restrict__ b2,   // [1]
    float* __restrict__ out)        // [512][512]  row=j, col=i
{
    __shared__ float pas[64][34];
    __shared__ float pbs[64][34];
    __shared__ float w2s[64];

    const int tid = threadIdx.x;
    const int ti = tid & 15;     // i pair
    const int tj = tid >> 4;     // j pair
    const int i0 = blockIdx.x * 32;
    const int j0 = blockIdx.y * 32;

    float acc00 = 0.f, acc01 = 0.f, acc10 = 0.f, acc11 = 0.f;

    for (int kc = 0; kc < MLPH; kc += 64) {
#pragma unroll
        for (int it = 0; it < 2; ++it) {
            int idx = tid + it * 256;
            int row = idx >> 4, q = idx & 15;
            float4 va = *(const float4*)&Pa[(long)(i0 + row) * MLPH + kc + 4 * q];
            pas[4 * q + 0][row] = va.x; pas[4 * q + 1][row] = va.y;
            pas[4 * q + 2][row] = va.z; pas[4 * q + 3][row] = va.w;
            float4 vb = *(const float4*)&Pb[(long)(j0 + row) * MLPH + kc + 4 * q];
            pbs[4 * q + 0][row] = vb.x; pbs[4 * q + 1][row] = vb.y;
            pbs[4 * q + 2][row] = vb.z; pbs[4 * q + 3][row] = vb.w;
        }
        if (tid < 16) {
            float4 w = *(const float4*)&W2[kc + 4 * tid];
            w2s[4 * tid + 0] = w.x; w2s[4 * tid + 1] = w.y;
            w2s[4 * tid + 2] = w.z; w2s[4 * tid + 3] = w.w;
        }
        __syncthreads();
#pragma unroll
        for (int kk = 0; kk < 64; ++kk) {
            float w = w2s[kk];
            float2 a = *(const float2*)&pas[kk][2 * ti];
            float2 b = *(const float2*)&pbs[kk][2 * tj];
            acc00 = fmaf(w, tanh_mufu(a.x + b.x), acc00);
            acc01 = fmaf(w, tanh_mufu(a.x + b.y), acc01);
            acc10 = fmaf(w, tanh_mufu(a.y + b.x), acc10);
            acc11 = fmaf(w, tanh_mufu(a.y + b.y), acc11);
        }
        __syncthreads();
    }

    float bb = b2[0];
    int i = i0 + 2 * ti;
    int j = j0 + 2 * tj;
    *(float2*)&out[(long)j * NN + i]       = make_float2(acc00 + bb, acc10 + bb);
    *(float2*)&out[(long)(j + 1) * NN + i] = make_float2(acc01 + bb, acc11 + bb);
}

// ---------------------------------------------------------------------------
// launch
// ---------------------------------------------------------------------------
extern "C" void kernel_launch(void* const* d_in, const int* in_sizes, int n_in,
                              void* d_out, int out_size)
{
    const float* x     = (const float*)d_in[0];   // (512,1,125)
    const float* Wih_f = (const float*)d_in[1];
    const float* Whh_f = (const float*)d_in[2];
    const float* bih_f = (const float*)d_in[3];
    const float* bhh_f = (const float*)d_in[4];
    const float* Wih_b = (const float*)d_in[5];
    const float* Whh_b = (const float*)d_in[6];
    const float* bih_b = (const float*)d_in[7];
    const float* bhh_b = (const float*)d_in[8];
    const float* W1    = (const float*)d_in[9];   // (512,500)
    const float* b1    = (const float*)d_in[10];  // (512)
    const float* W2    = (const float*)d_in[11];  // (1,512)
    const float* b2    = (const float*)d_in[12];  // (1)
    float* out = (float*)d_out;

    float *pA, *pH, *pP;
    cudaGetSymbolAddress((void**)&pA, g_A);
    cudaGetSymbolAddress((void**)&pH, g_H);
    cudaGetSymbolAddress((void**)&pP, g_P);
    float* pPa = pP;
    float* pPb = pP + NN * MLPH;

    cudaFuncSetAttribute(lstm_kernel,
                         cudaFuncAttributeMaxDynamicSharedMemorySize,
                         LSTM_SMEM_BYTES);

    dim3 blk(256);
    // keep launch-slot layout so ncu's captured launch stays on lstm_kernel
    nudge_kernel<<<1, 32>>>();
    nudge_kernel<<<1, 32>>>();
    proj_kernel<<<dim3(16, 16, 2), blk>>>(x, Wih_f, bih_f, bhh_f,
                                          Wih_b, bih_b, bhh_b, pA);
    lstm_kernel<<<2, 256, LSTM_SMEM_BYTES>>>(Whh_f, Whh_b, pA, pH);
    pab_kernel<<<dim3(16, 16, 2), blk>>>(pH, W1, b1, pP);
    pair_kernel<<<dim3(16, 16), blk>>>(pPa, pPb, W2, b2, out);
}

// round 8
// speedup vs baseline: 1.0394x; 1.0394x over previous
#include <cuda_runtime.h>
#include <cuda_bf16.h>
#include <math.h>

#define T_SEQ   512
#define GATES   500
#define HID     125
#define DHID    250      // 2*HID
#define MLPH    512
#define NN      512

// Scratch (device globals; no allocation allowed)
__device__ float g_A[2 * T_SEQ * GATES];   // input projections (fwd/bwd)
__device__ float g_H[T_SEQ * DHID];        // concat hidden states
__device__ float g_P[2 * NN * MLPH];       // Pa, Pb(+b1)

// ---------------------------------------------------------------------------
// helpers
// ---------------------------------------------------------------------------
typedef unsigned long long ull;

__device__ __forceinline__ ull ffma2u(ull a, ull b, ull c) {
    ull d;
    asm("fma.rn.f32x2 %0, %1, %2, %3;" : "=l"(d) : "l"(a), "l"(b), "l"(c));
    return d;
}
__device__ __forceinline__ ull fadd2u(ull a, ull b) {
    ull d;
    asm("add.rn.f32x2 %0, %1, %2;" : "=l"(d) : "l"(a), "l"(b));
    return d;
}
__device__ __forceinline__ float2 u2f2(ull v) {
    float2 r;
    asm("mov.b64 {%0, %1}, %2;" : "=f"(r.x), "=f"(r.y) : "l"(v));
    return r;
}
// unpack packed bf16x2 (lo16 = even col, hi16 = odd col) to packed f32x2
__device__ __forceinline__ ull unpk(unsigned int v) {
    ull d;
    asm("{\n\t"
        ".reg .b32 lo, hi;\n\t"
        "shl.b32 lo, %1, 16;\n\t"
        "and.b32 hi, %1, 0xFFFF0000;\n\t"
        "mov.b64 %0, {lo, hi};\n\t"
        "}" : "=l"(d) : "r"(v));
    return d;
}
__device__ __forceinline__ float tanh_mufu(float x) {
    float y;
    asm("tanh.approx.f32 %0, %1;" : "=f"(y) : "f"(x));
    return y;
}
__device__ __forceinline__ float sig_mufu(float x) {
    return 0.5f * tanh_mufu(0.5f * x) + 0.5f;
}

// no-op kernels to keep the ncu capture slot on lstm_kernel
__device__ int g_sink;
__global__ void nudge_kernel() {
    if (threadIdx.x > 4096) g_sink = 1;   // never taken
}

// ---------------------------------------------------------------------------
// Input projection, both directions in one launch.
// ---------------------------------------------------------------------------
__global__ void __launch_bounds__(256) proj_kernel(
    const float* __restrict__ x,
    const float* __restrict__ Wih_f, const float* __restrict__ bih_f,
    const float* __restrict__ bhh_f,
    const float* __restrict__ Wih_b, const float* __restrict__ bih_b,
    const float* __restrict__ bhh_b,
    float* __restrict__ Aout)
{
    const int dir = blockIdx.z;
    const float* __restrict__ W  = dir ? Wih_b : Wih_f;
    const float* __restrict__ bi = dir ? bih_b : bih_f;
    const float* __restrict__ bh = dir ? bhh_b : bhh_f;
    float* __restrict__ C = Aout + dir * (T_SEQ * GATES);

    __shared__ float As[16][34];
    __shared__ float Bs[16][34];

    const int tid = threadIdx.x;
    const int ti = tid & 15;
    const int tn = tid >> 4;
    const int m0 = blockIdx.x * 32;
    const int n0 = blockIdx.y * 32;

    float acc00 = 0.f, acc01 = 0.f, acc10 = 0.f, acc11 = 0.f;

    for (int kc = 0; kc < 125; kc += 16) {
#pragma unroll
        for (int it = 0; it < 2; ++it) {
            int idx = tid + it * 256;
            int mm = idx >> 4, kk = idx & 15;
            int k = kc + kk;
            int m = m0 + mm;
            int ra = dir ? (T_SEQ - 1 - m) : m;
            As[kk][mm] = (k < 125) ? x[(long)ra * 125 + k] : 0.f;
            int n = n0 + mm;
            Bs[kk][mm] = (n < GATES && k < 125) ? W[(long)n * 125 + k] : 0.f;
        }
        __syncthreads();
#pragma unroll
        for (int kk = 0; kk < 16; ++kk) {
            float2 av = *(const float2*)&As[kk][2 * ti];
            float2 bv = *(const float2*)&Bs[kk][2 * tn];
            acc00 = fmaf(av.x, bv.x, acc00);
            acc01 = fmaf(av.x, bv.y, acc01);
            acc10 = fmaf(av.y, bv.x, acc10);
            acc11 = fmaf(av.y, bv.y, acc11);
        }
        __syncthreads();
    }

    int m_ = m0 + 2 * ti;
    int n_ = n0 + 2 * tn;
    float b0 = 0.f, b1v = 0.f;
    if (n_ < GATES)     b0  = bi[n_] + bh[n_];
    if (n_ + 1 < GATES) b1v = bi[n_ + 1] + bh[n_ + 1];
    if (n_ < GATES) {
        C[(long)m_ * GATES + n_]       = acc00 + b0;
        C[(long)(m_ + 1) * GATES + n_] = acc10 + b0;
    }
    if (n_ + 1 < GATES) {
        C[(long)m_ * GATES + n_ + 1]       = acc01 + b1v;
        C[(long)(m_ + 1) * GATES + n_ + 1] = acc11 + b1v;
    }
}

// ---------------------------------------------------------------------------
// Pa / Pb in one launch. grid (16,16,2), block 256.
// ---------------------------------------------------------------------------
__global__ void __launch_bounds__(256) pab_kernel(
    const float* __restrict__ H,
    const float* __restrict__ W1,
    const float* __restrict__ b1,
    float* __restrict__ P)
{
    const int z = blockIdx.z;
    const float* __restrict__ B = W1 + (z ? DHID : 0);
    float* __restrict__ C = P + (long)z * NN * MLPH;

    __shared__ float As[16][34];
    __shared__ float Bs[16][34];

    const int tid = threadIdx.x;
    const int ti = tid & 15;
    const int tn = tid >> 4;
    const int m0 = blockIdx.x * 32;
    const int n0 = blockIdx.y * 32;

    float acc00 = 0.f, acc01 = 0.f, acc10 = 0.f, acc11 = 0.f;

    for (int kc = 0; kc < DHID; kc += 16) {
#pragma unroll
        for (int it = 0; it < 2; ++it) {
            int idx = tid + it * 256;
            int mm = idx >> 4, kk = idx & 15;
            int k = kc + kk;
            As[kk][mm] = (k < DHID) ? H[(long)(m0 + mm) * DHID + k] : 0.f;
            Bs[kk][mm] = (k < DHID) ? B[(long)(n0 + mm) * 500 + k] : 0.f;
        }
        __syncthreads();
#pragma unroll
        for (int kk = 0; kk < 16; ++kk) {
            float2 av = *(const float2*)&As[kk][2 * ti];
            float2 bv = *(const float2*)&Bs[kk][2 * tn];
            acc00 = fmaf(av.x, bv.x, acc00);
            acc01 = fmaf(av.x, bv.y, acc01);
            acc10 = fmaf(av.y, bv.x, acc10);
            acc11 = fmaf(av.y, bv.y, acc11);
        }
        __syncthreads();
    }

    int m_ = m0 + 2 * ti;
    int n_ = n0 + 2 * tn;
    float b0 = 0.f, b1v = 0.f;
    if (z) { b0 = b1[n_]; b1v = b1[n_ + 1]; }
    C[(long)m_ * MLPH + n_]           = acc00 + b0;
    C[(long)m_ * MLPH + n_ + 1]       = acc01 + b1v;
    C[(long)(m_ + 1) * MLPH + n_]     = acc10 + b0;
    C[(long)(m_ + 1) * MLPH + n_ + 1] = acc11 + b1v;
}

// ---------------------------------------------------------------------------
// LSTM recurrence, column-split. grid = 2 (dir), block = 512 (16 warps).
// Thread t: u = t & 127 (active u < 125), gp = (t>>7)&1, ch = t>>8.
//   gp 0 -> rows rA = u       (i),  rB = 250 + u (g)
//   gp 1 -> rows rA = 125 + u (f),  rB = 375 + u (o)
//   ch 0 -> cols 0..63    (reg cols 0..39,   bf16 smem cols 40..63)
//   ch 1 -> cols 64..127  (reg cols 64..103, bf16 smem cols 104..127; >=125 =0)
// ch1 writes its partial sums to smem; ch0 reduces + activates.
// gp0/ch0 writes i*g; gp1/ch0 owns c and h.
// Dynamic smem (bytes):
//   sh_wb : 6*500 uint4 = 48000
//   sh_pA : 256 floats, sh_pB : 256 floats
//   sh_ig : 128 floats, sh_h : 128 floats
// ---------------------------------------------------------------------------
#define LSTM_SMEM_BYTES (6 * 500 * 16 + 256 * 4 + 256 * 4 + 128 * 4 + 128 * 4)

__global__ void __launch_bounds__(512, 1) lstm_kernel(
    const float* __restrict__ Whh_f,
    const float* __restrict__ Whh_b,
    const float* __restrict__ A,     // [2][512][500]
    float* __restrict__ H)           // [512][250]
{
    extern __shared__ __align__(16) unsigned char dsm[];
    uint4* sh_wb = (uint4*)dsm;                                // 6*500
    float* sh_pA = (float*)(dsm + 6 * 500 * 16);               // 256
    float* sh_pB = sh_pA + 256;                                // 256
    float* sh_ig = sh_pB + 256;                                // 128
    float* sh_h  = sh_ig + 128;                                // 128

    const int tid = threadIdx.x;
    const int dir = blockIdx.x;
    const float* __restrict__ Whh = dir ? Whh_b : Whh_f;
    const float* __restrict__ Ad = A + dir * (T_SEQ * GATES);

    const int u  = tid & 127;
    const int gp = (tid >> 7) & 1;
    const int ch = tid >> 8;
    const bool act = (u < HID);
    const int rA = gp * 125 + u;          // i or f row
    const int rB = 250 + gp * 125 + u;    // g or o row

    // stage bf16 smem weights, layout [q][row]:
    //   q 0..2 -> cols 40 + 8q ; q 3..5 -> cols 104 + 8(q-3) (>=125 zero)
    for (int idx = tid; idx < 6 * 500; idx += 512) {
        int q = idx / 500, rr = idx - q * 500;
        int cb = (q < 3) ? (40 + 8 * q) : (104 + 8 * (q - 3));
        const float* w = Whh + rr * 125;
        unsigned int uu[4];
#pragma unroll
        for (int j = 0; j < 4; ++j) {
            int c0 = cb + 2 * j, c1 = c0 + 1;
            unsigned short b0 = (c0 < 125) ?
                __bfloat16_as_ushort(__float2bfloat16_rn(w[c0])) : 0;
            unsigned short b1 = (c1 < 125) ?
                __bfloat16_as_ushort(__float2bfloat16_rn(w[c1])) : 0;
            uu[j] = ((unsigned int)b1 << 16) | b0;
        }
        sh_wb[q * 500 + rr] = make_uint4(uu[0], uu[1], uu[2], uu[3]);
    }

    // register weights: 40 fp32 cols of both rows (cols 64*ch .. 64*ch+39)
    ull wA[20], wB[20];
    if (act) {
        const float* fA = Whh + rA * 125 + 64 * ch;
        const float* fB = Whh + rB * 125 + 64 * ch;
#pragma unroll
        for (int p = 0; p < 20; ++p) {
            float2 tA = make_float2(fA[2 * p], fA[2 * p + 1]);
            float2 tB = make_float2(fB[2 * p], fB[2 * p + 1]);
            wA[p] = *(ull*)&tA;
            wB[p] = *(ull*)&tB;
        }
    }

    if (tid < 128) sh_h[tid] = 0.f;   // includes pad slots 125..127
    float creg = 0.f;
    const bool ld_a = act && (ch == 0);
    float aA = ld_a ? Ad[rA] : 0.f;
    float aB = ld_a ? Ad[rB] : 0.f;
    __syncthreads();

    const ulonglong2* h2 = (const ulonglong2*)sh_h;   // 32 granules of 16B
    const int G = 16 * ch;          // this thread's h granule base
    const int qb = 3 * ch;          // this thread's bf16 q base
    const int pidx = gp * 128 + u;  // partial-sum slot

    for (int t = 0; t < T_SEQ; ++t) {
        const bool has_next = (t < T_SEQ - 1);
        float aA_n = (ld_a && has_next) ? Ad[(t + 1) * GATES + rA] : 0.f;
        float aB_n = (ld_a && has_next) ? Ad[(t + 1) * GATES + rB] : 0.f;

        float sA_p = 0.f, sB_p = 0.f;
        if (act) {
            ull accA0 = 0ull, accA1 = 0ull, accB0 = 0ull, accB1 = 0ull;
#pragma unroll
            for (int p = 0; p < 10; ++p) {     // 40 reg cols (10 granules)
                ulonglong2 hv = h2[G + p];
                accA0 = ffma2u(wA[2 * p],     hv.x, accA0);
                accA1 = ffma2u(wA[2 * p + 1], hv.y, accA1);
                accB0 = ffma2u(wB[2 * p],     hv.x, accB0);
                accB1 = ffma2u(wB[2 * p + 1], hv.y, accB1);
            }
#pragma unroll
            for (int q = 0; q < 3; ++q) {      // 24 bf16 cols (6 granules)
                ulonglong2 ha = h2[G + 10 + 2 * q];
                ulonglong2 hb = h2[G + 11 + 2 * q];
                uint4 wa = sh_wb[(qb + q) * 500 + rA];
                uint4 wb = sh_wb[(qb + q) * 500 + rB];
                accA0 = ffma2u(unpk(wa.x), ha.x, accA0);
                accA1 = ffma2u(unpk(wa.y), ha.y, accA1);
                accA0 = ffma2u(unpk(wa.z), hb.x, accA0);
                accA1 = ffma2u(unpk(wa.w), hb.y, accA1);
                accB0 = ffma2u(unpk(wb.x), ha.x, accB0);
                accB1 = ffma2u(unpk(wb.y), ha.y, accB1);
                accB0 = ffma2u(unpk(wb.z), hb.x, accB0);
                accB1 = ffma2u(unpk(wb.w), hb.y, accB1);
            }
            float2 fa = u2f2(fadd2u(accA0, accA1));
            float2 fb = u2f2(fadd2u(accB0, accB1));
            sA_p = fa.x + fa.y;
            sB_p = fb.x + fb.y;
            if (ch == 1) {
                sh_pA[pidx] = sA_p;
                sh_pB[pidx] = sB_p;
            }
        }
        __syncthreads();

        float fv = 0.f, ov = 0.f;     // live only on gp1/ch0
        if (act && ch == 0) {
            float sA = sA_p + sh_pA[pidx] + aA;
            float sB = sB_p + sh_pB[pidx] + aB;
            if (gp == 0) {
                float iv = sig_mufu(sA);
                float gv = tanh_mufu(sB);
                sh_ig[u] = iv * gv;
            } else {
                fv = sig_mufu(sA);
                ov = sig_mufu(sB);
            }
        }
        __syncthreads();

        if (act && ch == 0 && gp == 1) {
            creg = fv * creg + sh_ig[u];
            float hv = ov * tanh_mufu(creg);
            sh_h[u] = hv;
            int row = dir ? (T_SEQ - 1 - t) : t;
            H[row * DHID + dir * HID + u] = hv;
        }
        __syncthreads();
        aA = aA_n; aB = aB_n;
    }
}

// ---------------------------------------------------------------------------
// Pairwise MLP contraction:
//   out[j][i] = b2 + sum_k W2[k] * tanh(Pa[i][k] + Pb[j][k])
// ---------------------------------------------------------------------------
__global__ void __launch_bounds__(256) pair_kernel(
    const float* __restrict__ Pa,   // [512][512]
    const float* __restrict__ Pb,   // [512][512] (b1 folded in)
    const float* __restrict__ W2,   // [512]
    const float* __restrict__ b2,   // [1]
    float* __restrict__ out)        // [512][512]  row=j, col=i
{
    __shared__ float pas[64][34];
    __shared__ float pbs[64][34];
    __shared__ float w2s[64];

    const int tid = threadIdx.x;
    const int ti = tid & 15;     // i pair
    const int tj = tid >> 4;     // j pair
    const int i0 = blockIdx.x * 32;
    const int j0 = blockIdx.y * 32;

    float acc00 = 0.f, acc01 = 0.f, acc10 = 0.f, acc11 = 0.f;

    for (int kc = 0; kc < MLPH; kc += 64) {
#pragma unroll
        for (int it = 0; it < 2; ++it) {
            int idx = tid + it * 256;
            int row = idx >> 4, q = idx & 15;
            float4 va = *(const float4*)&Pa[(long)(i0 + row) * MLPH + kc + 4 * q];
            pas[4 * q + 0][row] = va.x; pas[4 * q + 1][row] = va.y;
            pas[4 * q + 2][row] = va.z; pas[4 * q + 3][row] = va.w;
            float4 vb = *(const float4*)&Pb[(long)(j0 + row) * MLPH + kc + 4 * q];
            pbs[4 * q + 0][row] = vb.x; pbs[4 * q + 1][row] = vb.y;
            pbs[4 * q + 2][row] = vb.z; pbs[4 * q + 3][row] = vb.w;
        }
        if (tid < 16) {
            float4 w = *(const float4*)&W2[kc + 4 * tid];
            w2s[4 * tid + 0] = w.x; w2s[4 * tid + 1] = w.y;
            w2s[4 * tid + 2] = w.z; w2s[4 * tid + 3] = w.w;
        }
        __syncthreads();
#pragma unroll
        for (int kk = 0; kk < 64; ++kk) {
            float w = w2s[kk];
            float2 a = *(const float2*)&pas[kk][2 * ti];
            float2 b = *(const float2*)&pbs[kk][2 * tj];
            acc00 = fmaf(w, tanh_mufu(a.x + b.x), acc00);
            acc01 = fmaf(w, tanh_mufu(a.x + b.y), acc01);
            acc10 = fmaf(w, tanh_mufu(a.y + b.x), acc10);
            acc11 = fmaf(w, tanh_mufu(a.y + b.y), acc11);
        }
        __syncthreads();
    }

    float bb = b2[0];
    int i = i0 + 2 * ti;
    int j = j0 + 2 * tj;
    *(float2*)&out[(long)j * NN + i]       = make_float2(acc00 + bb, acc10 + bb);
    *(float2*)&out[(long)(j + 1) * NN + i] = make_float2(acc01 + bb, acc11 + bb);
}

// ---------------------------------------------------------------------------
// launch
// ---------------------------------------------------------------------------
extern "C" void kernel_launch(void* const* d_in, const int* in_sizes, int n_in,
                              void* d_out, int out_size)
{
    const float* x     = (const float*)d_in[0];   // (512,1,125)
    const float* Wih_f = (const float*)d_in[1];
    const float* Whh_f = (const float*)d_in[2];
    const float* bih_f = (const float*)d_in[3];
    const float* bhh_f = (const float*)d_in[4];
    const float* Wih_b = (const float*)d_in[5];
    const float* Whh_b = (const float*)d_in[6];
    const float* bih_b = (const float*)d_in[7];
    const float* bhh_b = (const float*)d_in[8];
    const float* W1    = (const float*)d_in[9];   // (512,500)
    const float* b1    = (const float*)d_in[10];  // (512)
    const float* W2    = (const float*)d_in[11];  // (1,512)
    const float* b2    = (const float*)d_in[12];  // (1)
    float* out = (float*)d_out;

    float *pA, *pH, *pP;
    cudaGetSymbolAddress((void**)&pA, g_A);
    cudaGetSymbolAddress((void**)&pH, g_H);
    cudaGetSymbolAddress((void**)&pP, g_P);
    float* pPa = pP;
    float* pPb = pP + NN * MLPH;

    cudaFuncSetAttribute(lstm_kernel,
                         cudaFuncAttributeMaxDynamicSharedMemorySize,
                         LSTM_SMEM_BYTES);

    dim3 blk(256);
    // keep launch-slot layout so ncu's captured launch stays on lstm_kernel
    nudge_kernel<<<1, 32>>>();
    nudge_kernel<<<1, 32>>>();
    proj_kernel<<<dim3(16, 16, 2), blk>>>(x, Wih_f, bih_f, bhh_f,
                                          Wih_b, bih_b, bhh_b, pA);
    lstm_kernel<<<2, 512, LSTM_SMEM_BYTES>>>(Whh_f, Whh_b, pA, pH);
    pab_kernel<<<dim3(16, 16, 2), blk>>>(pH, W1, b1, pP);
    pair_kernel<<<dim3(16, 16), blk>>>(pPa, pPb, W2, b2, out);
}

// round 9
// speedup vs baseline: 1.1091x; 1.0671x over previous
#include <cuda_runtime.h>
#include <cuda_bf16.h>
#include <math.h>

#define T_SEQ   512
#define GATES   500
#define HID     125
#define DHID    250      // 2*HID
#define MLPH    512
#define NN      512

// Scratch (device globals; no allocation allowed)
__device__ float g_A[2 * T_SEQ * GATES];   // input projections (fwd/bwd)
__device__ float g_H[T_SEQ * DHID];        // concat hidden states
__device__ float g_P[2 * NN * MLPH];       // Pa, Pb(+b1)

// ---------------------------------------------------------------------------
// helpers
// ---------------------------------------------------------------------------
typedef unsigned long long ull;

__device__ __forceinline__ ull ffma2u(ull a, ull b, ull c) {
    ull d;
    asm("fma.rn.f32x2 %0, %1, %2, %3;" : "=l"(d) : "l"(a), "l"(b), "l"(c));
    return d;
}
__device__ __forceinline__ ull fadd2u(ull a, ull b) {
    ull d;
    asm("add.rn.f32x2 %0, %1, %2;" : "=l"(d) : "l"(a), "l"(b));
    return d;
}
__device__ __forceinline__ float2 u2f2(ull v) {
    float2 r;
    asm("mov.b64 {%0, %1}, %2;" : "=f"(r.x), "=f"(r.y) : "l"(v));
    return r;
}
// unpack packed bf16x2 (lo16 = even col, hi16 = odd col) to packed f32x2
__device__ __forceinline__ ull unpk(unsigned int v) {
    ull d;
    asm("{\n\t"
        ".reg .b32 lo, hi;\n\t"
        "shl.b32 lo, %1, 16;\n\t"
        "and.b32 hi, %1, 0xFFFF0000;\n\t"
        "mov.b64 %0, {lo, hi};\n\t"
        "}" : "=l"(d) : "r"(v));
    return d;
}
__device__ __forceinline__ float tanh_mufu(float x) {
    float y;
    asm("tanh.approx.f32 %0, %1;" : "=f"(y) : "f"(x));
    return y;
}
__device__ __forceinline__ float sig_mufu(float x) {
    return 0.5f * tanh_mufu(0.5f * x) + 0.5f;
}

// no-op kernels to keep the ncu capture slot on lstm_kernel
__device__ int g_sink;
__global__ void nudge_kernel() {
    if (threadIdx.x > 4096) g_sink = 1;   // never taken
}

// ---------------------------------------------------------------------------
// Input projection, both directions in one launch.
// ---------------------------------------------------------------------------
__global__ void __launch_bounds__(256) proj_kernel(
    const float* __restrict__ x,
    const float* __restrict__ Wih_f, const float* __restrict__ bih_f,
    const float* __restrict__ bhh_f,
    const float* __restrict__ Wih_b, const float* __restrict__ bih_b,
    const float* __restrict__ bhh_b,
    float* __restrict__ Aout)
{
    const int dir = blockIdx.z;
    const float* __restrict__ W  = dir ? Wih_b : Wih_f;
    const float* __restrict__ bi = dir ? bih_b : bih_f;
    const float* __restrict__ bh = dir ? bhh_b : bhh_f;
    float* __restrict__ C = Aout + dir * (T_SEQ * GATES);

    __shared__ float As[16][34];
    __shared__ float Bs[16][34];

    const int tid = threadIdx.x;
    const int ti = tid & 15;
    const int tn = tid >> 4;
    const int m0 = blockIdx.x * 32;
    const int n0 = blockIdx.y * 32;

    float acc00 = 0.f, acc01 = 0.f, acc10 = 0.f, acc11 = 0.f;

    for (int kc = 0; kc < 125; kc += 16) {
#pragma unroll
        for (int it = 0; it < 2; ++it) {
            int idx = tid + it * 256;
            int mm = idx >> 4, kk = idx & 15;
            int k = kc + kk;
            int m = m0 + mm;
            int ra = dir ? (T_SEQ - 1 - m) : m;
            As[kk][mm] = (k < 125) ? x[(long)ra * 125 + k] : 0.f;
            int n = n0 + mm;
            Bs[kk][mm] = (n < GATES && k < 125) ? W[(long)n * 125 + k] : 0.f;
        }
        __syncthreads();
#pragma unroll
        for (int kk = 0; kk < 16; ++kk) {
            float2 av = *(const float2*)&As[kk][2 * ti];
            float2 bv = *(const float2*)&Bs[kk][2 * tn];
            acc00 = fmaf(av.x, bv.x, acc00);
            acc01 = fmaf(av.x, bv.y, acc01);
            acc10 = fmaf(av.y, bv.x, acc10);
            acc11 = fmaf(av.y, bv.y, acc11);
        }
        __syncthreads();
    }

    int m_ = m0 + 2 * ti;
    int n_ = n0 + 2 * tn;
    float b0 = 0.f, b1v = 0.f;
    if (n_ < GATES)     b0  = bi[n_] + bh[n_];
    if (n_ + 1 < GATES) b1v = bi[n_ + 1] + bh[n_ + 1];
    if (n_ < GATES) {
        C[(long)m_ * GATES + n_]       = acc00 + b0;
        C[(long)(m_ + 1) * GATES + n_] = acc10 + b0;
    }
    if (n_ + 1 < GATES) {
        C[(long)m_ * GATES + n_ + 1]       = acc01 + b1v;
        C[(long)(m_ + 1) * GATES + n_ + 1] = acc11 + b1v;
    }
}

// ---------------------------------------------------------------------------
// Pa / Pb in one launch. grid (16,16,2), block 256.
// ---------------------------------------------------------------------------
__global__ void __launch_bounds__(256) pab_kernel(
    const float* __restrict__ H,
    const float* __restrict__ W1,
    const float* __restrict__ b1,
    float* __restrict__ P)
{
    const int z = blockIdx.z;
    const float* __restrict__ B = W1 + (z ? DHID : 0);
    float* __restrict__ C = P + (long)z * NN * MLPH;

    __shared__ float As[16][34];
    __shared__ float Bs[16][34];

    const int tid = threadIdx.x;
    const int ti = tid & 15;
    const int tn = tid >> 4;
    const int m0 = blockIdx.x * 32;
    const int n0 = blockIdx.y * 32;

    float acc00 = 0.f, acc01 = 0.f, acc10 = 0.f, acc11 = 0.f;

    for (int kc = 0; kc < DHID; kc += 16) {
#pragma unroll
        for (int it = 0; it < 2; ++it) {
            int idx = tid + it * 256;
            int mm = idx >> 4, kk = idx & 15;
            int k = kc + kk;
            As[kk][mm] = (k < DHID) ? H[(long)(m0 + mm) * DHID + k] : 0.f;
            Bs[kk][mm] = (k < DHID) ? B[(long)(n0 + mm) * 500 + k] : 0.f;
        }
        __syncthreads();
#pragma unroll
        for (int kk = 0; kk < 16; ++kk) {
            float2 av = *(const float2*)&As[kk][2 * ti];
            float2 bv = *(const float2*)&Bs[kk][2 * tn];
            acc00 = fmaf(av.x, bv.x, acc00);
            acc01 = fmaf(av.x, bv.y, acc01);
            acc10 = fmaf(av.y, bv.x, acc10);
            acc11 = fmaf(av.y, bv.y, acc11);
        }
        __syncthreads();
    }

    int m_ = m0 + 2 * ti;
    int n_ = n0 + 2 * tn;
    float b0 = 0.f, b1v = 0.f;
    if (z) { b0 = b1[n_]; b1v = b1[n_ + 1]; }
    C[(long)m_ * MLPH + n_]           = acc00 + b0;
    C[(long)m_ * MLPH + n_ + 1]       = acc01 + b1v;
    C[(long)(m_ + 1) * MLPH + n_]     = acc10 + b0;
    C[(long)(m_ + 1) * MLPH + n_ + 1] = acc11 + b1v;
}

// ---------------------------------------------------------------------------
// LSTM recurrence, 2 rows per thread + explicit prefetch rings.
// grid = 2 (dir), block = 256.
// Thread t: u = t & 127 (active u < 125), gp = t >> 7.
//   gp 0 -> rows rA = u       (i),  rB = 250 + u (g)
//   gp 1 -> rows rA = 125 + u (f),  rB = 375 + u (o)
// Weights: cols 0..79 fp32 in registers (2x40 ull), cols 80..127 bf16 in smem
//   as uint2 per 4-col granule (cols >=125 zero).
// 32 h-granules of 16B; granules 0..19 use reg weights, 20..31 bf16 smem.
// h ring depth 4; weight ring depth 4 (load at g-4, use at g).
// Update: gp0 writes i*g; gp1 owns c: c = f*c + ig; h = o*tanh(c).
// ---------------------------------------------------------------------------
__global__ void __launch_bounds__(256, 1) lstm_kernel(
    const float* __restrict__ Whh_f,
    const float* __restrict__ Whh_b,
    const float* __restrict__ A,     // [2][512][500]
    float* __restrict__ H)           // [512][250]
{
    __shared__ __align__(16) uint2 sh_wb[12 * 500];   // 48000 B
    __shared__ __align__(16) float sh_ig[128];
    __shared__ __align__(16) float sh_h[128];

    const int tid = threadIdx.x;
    const int dir = blockIdx.x;
    const float* __restrict__ Whh = dir ? Whh_b : Whh_f;
    const float* __restrict__ Ad = A + dir * (T_SEQ * GATES);

    const int u  = tid & 127;
    const int gp = tid >> 7;
    const bool act = (u < HID);
    const int rA = gp * 125 + u;          // i or f row
    const int rB = 250 + gp * 125 + u;    // g or o row

    // stage bf16 smem weights: granule gg -> cols 80+4gg .. 83+4gg (>=125 -> 0)
    for (int idx = tid; idx < 12 * 500; idx += 256) {
        int gg = idx / 500, rr = idx - gg * 500;
        const float* w = Whh + rr * 125;
        int c = 80 + 4 * gg;
        unsigned short b0 = (c + 0 < 125) ?
            __bfloat16_as_ushort(__float2bfloat16_rn(w[c + 0])) : 0;
        unsigned short b1 = (c + 1 < 125) ?
            __bfloat16_as_ushort(__float2bfloat16_rn(w[c + 1])) : 0;
        unsigned short b2 = (c + 2 < 125) ?
            __bfloat16_as_ushort(__float2bfloat16_rn(w[c + 2])) : 0;
        unsigned short b3 = (c + 3 < 125) ?
            __bfloat16_as_ushort(__float2bfloat16_rn(w[c + 3])) : 0;
        sh_wb[gg * 500 + rr] =
            make_uint2(((unsigned int)b1 << 16) | b0,
                       ((unsigned int)b3 << 16) | b2);
    }

    // register weights: cols 0..79 of both rows, packed ull
    ull wA[40], wB[40];
    if (act) {
        const float* fA = Whh + rA * 125;
        const float* fB = Whh + rB * 125;
#pragma unroll
        for (int p = 0; p < 40; ++p) {
            float2 tA = make_float2(fA[2 * p], fA[2 * p + 1]);
            float2 tB = make_float2(fB[2 * p], fB[2 * p + 1]);
            wA[p] = *(ull*)&tA;
            wB[p] = *(ull*)&tB;
        }
    }

    if (tid < 128) sh_h[tid] = 0.f;   // includes pad slots 125..127
    float creg = 0.f;
    float aA = act ? Ad[rA] : 0.f;
    float aB = act ? Ad[rB] : 0.f;
    __syncthreads();

    const ulonglong2* h2 = (const ulonglong2*)sh_h;   // 32 granules of 16B

    for (int t = 0; t < T_SEQ; ++t) {
        const bool has_next = (t < T_SEQ - 1);
        float aA_n = (act && has_next) ? Ad[(t + 1) * GATES + rA] : 0.f;
        float aB_n = (act && has_next) ? Ad[(t + 1) * GATES + rB] : 0.f;

        float fv = 0.f, ov = 0.f;   // gp1's f and o
        if (act) {
            ull accA0 = 0ull, accA1 = 0ull, accB0 = 0ull, accB1 = 0ull;
            ulonglong2 hr[4];
            uint2 war[4], wbr[4];
#pragma unroll
            for (int k = 0; k < 4; ++k) hr[k] = h2[k];
#pragma unroll
            for (int g = 0; g < 32; ++g) {
                ulonglong2 hv = hr[g & 3];
                if (g + 4 < 32) hr[g & 3] = h2[g + 4];
                ull w0A, w1A, w0B, w1B;
                if (g < 20) {
                    w0A = wA[2 * g];     w1A = wA[2 * g + 1];
                    w0B = wB[2 * g];     w1B = wB[2 * g + 1];
                } else {
                    uint2 wa = war[g & 3], wb = wbr[g & 3];
                    w0A = unpk(wa.x);    w1A = unpk(wa.y);
                    w0B = unpk(wb.x);    w1B = unpk(wb.y);
                }
                if (g >= 16 && g < 28) {   // load granule g+4's weights
                    war[g & 3] = sh_wb[(g - 16) * 500 + rA];
                    wbr[g & 3] = sh_wb[(g - 16) * 500 + rB];
                }
                accA0 = ffma2u(w0A, hv.x, accA0);
                accA1 = ffma2u(w1A, hv.y, accA1);
                accB0 = ffma2u(w0B, hv.x, accB0);
                accB1 = ffma2u(w1B, hv.y, accB1);
            }
            float2 fa = u2f2(fadd2u(accA0, accA1));
            float2 fb = u2f2(fadd2u(accB0, accB1));
            float sA = fa.x + fa.y + aA;
            float sB = fb.x + fb.y + aB;
            if (gp == 0) {
                sh_ig[u] = sig_mufu(sA) * tanh_mufu(sB);   // i*g
            } else {
                fv = sig_mufu(sA);
                ov = sig_mufu(sB);
            }
        }
        __syncthreads();
        if (act && gp == 1) {
            creg = fv * creg + sh_ig[u];
            float hv = ov * tanh_mufu(creg);
            sh_h[u] = hv;
            int row = dir ? (T_SEQ - 1 - t) : t;
            H[row * DHID + dir * HID + u] = hv;
        }
        __syncthreads();
        aA = aA_n; aB = aB_n;
    }
}

// ---------------------------------------------------------------------------
// Pairwise MLP contraction:
//   out[j][i] = b2 + sum_k W2[k] * tanh(Pa[i][k] + Pb[j][k])
// ---------------------------------------------------------------------------
__global__ void __launch_bounds__(256) pair_kernel(
    const float* __restrict__ Pa,   // [512][512]
    const float* __restrict__ Pb,   // [512][512] (b1 folded in)
    const float* __restrict__ W2,   // [512]
    const float* __restrict__ b2,   // [1]
    float* __restrict__ out)        // [512][512]  row=j, col=i
{
    __shared__ float pas[64][34];
    __shared__ float pbs[64][34];
    __shared__ float w2s[64];

    const int tid = threadIdx.x;
    const int ti = tid & 15;     // i pair
    const int tj = tid >> 4;     // j pair
    const int i0 = blockIdx.x * 32;
    const int j0 = blockIdx.y * 32;

    float acc00 = 0.f, acc01 = 0.f, acc10 = 0.f, acc11 = 0.f;

    for (int kc = 0; kc < MLPH; kc += 64) {
#pragma unroll
        for (int it = 0; it < 2; ++it) {
            int idx = tid + it * 256;
            int row = idx >> 4, q = idx & 15;
            float4 va = *(const float4*)&Pa[(long)(i0 + row) * MLPH + kc + 4 * q];
            pas[4 * q + 0][row] = va.x; pas[4 * q + 1][row] = va.y;
            pas[4 * q + 2][row] = va.z; pas[4 * q + 3][row] = va.w;
            float4 vb = *(const float4*)&Pb[(long)(j0 + row) * MLPH + kc + 4 * q];
            pbs[4 * q + 0][row] = vb.x; pbs[4 * q + 1][row] = vb.y;
            pbs[4 * q + 2][row] = vb.z; pbs[4 * q + 3][row] = vb.w;
        }
        if (tid < 16) {
            float4 w = *(const float4*)&W2[kc + 4 * tid];
            w2s[4 * tid + 0] = w.x; w2s[4 * tid + 1] = w.y;
            w2s[4 * tid + 2] = w.z; w2s[4 * tid + 3] = w.w;
        }
        __syncthreads();
#pragma unroll
        for (int kk = 0; kk < 64; ++kk) {
            float w = w2s[kk];
            float2 a = *(const float2*)&pas[kk][2 * ti];
            float2 b = *(const float2*)&pbs[kk][2 * tj];
            acc00 = fmaf(w, tanh_mufu(a.x + b.x), acc00);
            acc01 = fmaf(w, tanh_mufu(a.x + b.y), acc01);
            acc10 = fmaf(w, tanh_mufu(a.y + b.x), acc10);
            acc11 = fmaf(w, tanh_mufu(a.y + b.y), acc11);
        }
        __syncthreads();
    }

    float bb = b2[0];
    int i = i0 + 2 * ti;
    int j = j0 + 2 * tj;
    *(float2*)&out[(long)j * NN + i]       = make_float2(acc00 + bb, acc10 + bb);
    *(float2*)&out[(long)(j + 1) * NN + i] = make_float2(acc01 + bb, acc11 + bb);
}

// ---------------------------------------------------------------------------
// launch
// ---------------------------------------------------------------------------
extern "C" void kernel_launch(void* const* d_in, const int* in_sizes, int n_in,
                              void* d_out, int out_size)
{
    const float* x     = (const float*)d_in[0];   // (512,1,125)
    const float* Wih_f = (const float*)d_in[1];
    const float* Whh_f = (const float*)d_in[2];
    const float* bih_f = (const float*)d_in[3];
    const float* bhh_f = (const float*)d_in[4];
    const float* Wih_b = (const float*)d_in[5];
    const float* Whh_b = (const float*)d_in[6];
    const float* bih_b = (const float*)d_in[7];
    const float* bhh_b = (const float*)d_in[8];
    const float* W1    = (const float*)d_in[9];   // (512,500)
    const float* b1    = (const float*)d_in[10];  // (512)
    const float* W2    = (const float*)d_in[11];  // (1,512)
    const float* b2    = (const float*)d_in[12];  // (1)
    float* out = (float*)d_out;

    float *pA, *pH, *pP;
    cudaGetSymbolAddress((void**)&pA, g_A);
    cudaGetSymbolAddress((void**)&pH, g_H);
    cudaGetSymbolAddress((void**)&pP, g_P);
    float* pPa = pP;
    float* pPb = pP + NN * MLPH;

    dim3 blk(256);
    // keep launch-slot layout so ncu's captured launch stays on lstm_kernel
    nudge_kernel<<<1, 32>>>();
    nudge_kernel<<<1, 32>>>();
    proj_kernel<<<dim3(16, 16, 2), blk>>>(x, Wih_f, bih_f, bhh_f,
                                          Wih_b, bih_b, bhh_b, pA);
    lstm_kernel<<<2, 256>>>(Whh_f, Whh_b, pA, pH);
    pab_kernel<<<dim3(16, 16, 2), blk>>>(pH, W1, b1, pP);
    pair_kernel<<<dim3(16, 16), blk>>>(pPa, pPb, W2, b2, out);
}

// round 10
// speedup vs baseline: 1.2163x; 1.0967x over previous
#include <cuda_runtime.h>
#include <cuda_bf16.h>
#include <math.h>

#define T_SEQ   512
#define GATES   500
#define HID     125
#define DHID    250      // 2*HID
#define MLPH    512
#define NN      512

// Scratch (device globals; no allocation allowed)
__device__ float g_A[2 * T_SEQ * GATES];   // input projections (fwd/bwd)
__device__ float g_H[T_SEQ * DHID];        // concat hidden states
__device__ float g_P[2 * NN * MLPH];       // Pa, Pb(+b1)

// ---------------------------------------------------------------------------
// helpers
// ---------------------------------------------------------------------------
typedef unsigned long long ull;

__device__ __forceinline__ ull ffma2u(ull a, ull b, ull c) {
    ull d;
    asm("fma.rn.f32x2 %0, %1, %2, %3;" : "=l"(d) : "l"(a), "l"(b), "l"(c));
    return d;
}
__device__ __forceinline__ ull fadd2u(ull a, ull b) {
    ull d;
    asm("add.rn.f32x2 %0, %1, %2;" : "=l"(d) : "l"(a), "l"(b));
    return d;
}
__device__ __forceinline__ float2 u2f2(ull v) {
    float2 r;
    asm("mov.b64 {%0, %1}, %2;" : "=f"(r.x), "=f"(r.y) : "l"(v));
    return r;
}
// unpack packed bf16x2 (lo16 = even col, hi16 = odd col) to packed f32x2
__device__ __forceinline__ ull unpk(unsigned int v) {
    ull d;
    asm("{\n\t"
        ".reg .b32 lo, hi;\n\t"
        "shl.b32 lo, %1, 16;\n\t"
        "and.b32 hi, %1, 0xFFFF0000;\n\t"
        "mov.b64 %0, {lo, hi};\n\t"
        "}" : "=l"(d) : "r"(v));
    return d;
}
__device__ __forceinline__ float tanh_mufu(float x) {
    float y;
    asm("tanh.approx.f32 %0, %1;" : "=f"(y) : "f"(x));
    return y;
}
__device__ __forceinline__ float sig_mufu(float x) {
    return 0.5f * tanh_mufu(0.5f * x) + 0.5f;
}

// no-op kernels to keep the ncu capture slot on lstm_kernel
__device__ int g_sink;
__global__ void nudge_kernel() {
    if (threadIdx.x > 4096) g_sink = 1;   // never taken
}

// ---------------------------------------------------------------------------
// Input projection, both directions in one launch.
// ---------------------------------------------------------------------------
__global__ void __launch_bounds__(256) proj_kernel(
    const float* __restrict__ x,
    const float* __restrict__ Wih_f, const float* __restrict__ bih_f,
    const float* __restrict__ bhh_f,
    const float* __restrict__ Wih_b, const float* __restrict__ bih_b,
    const float* __restrict__ bhh_b,
    float* __restrict__ Aout)
{
    const int dir = blockIdx.z;
    const float* __restrict__ W  = dir ? Wih_b : Wih_f;
    const float* __restrict__ bi = dir ? bih_b : bih_f;
    const float* __restrict__ bh = dir ? bhh_b : bhh_f;
    float* __restrict__ C = Aout + dir * (T_SEQ * GATES);

    __shared__ float As[16][34];
    __shared__ float Bs[16][34];

    const int tid = threadIdx.x;
    const int ti = tid & 15;
    const int tn = tid >> 4;
    const int m0 = blockIdx.x * 32;
    const int n0 = blockIdx.y * 32;

    float acc00 = 0.f, acc01 = 0.f, acc10 = 0.f, acc11 = 0.f;

    for (int kc = 0; kc < 125; kc += 16) {
#pragma unroll
        for (int it = 0; it < 2; ++it) {
            int idx = tid + it * 256;
            int mm = idx >> 4, kk = idx & 15;
            int k = kc + kk;
            int m = m0 + mm;
            int ra = dir ? (T_SEQ - 1 - m) : m;
            As[kk][mm] = (k < 125) ? x[(long)ra * 125 + k] : 0.f;
            int n = n0 + mm;
            Bs[kk][mm] = (n < GATES && k < 125) ? W[(long)n * 125 + k] : 0.f;
        }
        __syncthreads();
#pragma unroll
        for (int kk = 0; kk < 16; ++kk) {
            float2 av = *(const float2*)&As[kk][2 * ti];
            float2 bv = *(const float2*)&Bs[kk][2 * tn];
            acc00 = fmaf(av.x, bv.x, acc00);
            acc01 = fmaf(av.x, bv.y, acc01);
            acc10 = fmaf(av.y, bv.x, acc10);
            acc11 = fmaf(av.y, bv.y, acc11);
        }
        __syncthreads();
    }

    int m_ = m0 + 2 * ti;
    int n_ = n0 + 2 * tn;
    float b0 = 0.f, b1v = 0.f;
    if (n_ < GATES)     b0  = bi[n_] + bh[n_];
    if (n_ + 1 < GATES) b1v = bi[n_ + 1] + bh[n_ + 1];
    if (n_ < GATES) {
        C[(long)m_ * GATES + n_]       = acc00 + b0;
        C[(long)(m_ + 1) * GATES + n_] = acc10 + b0;
    }
    if (n_ + 1 < GATES) {
        C[(long)m_ * GATES + n_ + 1]       = acc01 + b1v;
        C[(long)(m_ + 1) * GATES + n_ + 1] = acc11 + b1v;
    }
}

// ---------------------------------------------------------------------------
// Pa / Pb in one launch. grid (16,16,2), block 256.
// ---------------------------------------------------------------------------
__global__ void __launch_bounds__(256) pab_kernel(
    const float* __restrict__ H,
    const float* __restrict__ W1,
    const float* __restrict__ b1,
    float* __restrict__ P)
{
    const int z = blockIdx.z;
    const float* __restrict__ B = W1 + (z ? DHID : 0);
    float* __restrict__ C = P + (long)z * NN * MLPH;

    __shared__ float As[16][34];
    __shared__ float Bs[16][34];

    const int tid = threadIdx.x;
    const int ti = tid & 15;
    const int tn = tid >> 4;
    const int m0 = blockIdx.x * 32;
    const int n0 = blockIdx.y * 32;

    float acc00 = 0.f, acc01 = 0.f, acc10 = 0.f, acc11 = 0.f;

    for (int kc = 0; kc < DHID; kc += 16) {
#pragma unroll
        for (int it = 0; it < 2; ++it) {
            int idx = tid + it * 256;
            int mm = idx >> 4, kk = idx & 15;
            int k = kc + kk;
            As[kk][mm] = (k < DHID) ? H[(long)(m0 + mm) * DHID + k] : 0.f;
            Bs[kk][mm] = (k < DHID) ? B[(long)(n0 + mm) * 500 + k] : 0.f;
        }
        __syncthreads();
#pragma unroll
        for (int kk = 0; kk < 16; ++kk) {
            float2 av = *(const float2*)&As[kk][2 * ti];
            float2 bv = *(const float2*)&Bs[kk][2 * tn];
            acc00 = fmaf(av.x, bv.x, acc00);
            acc01 = fmaf(av.x, bv.y, acc01);
            acc10 = fmaf(av.y, bv.x, acc10);
            acc11 = fmaf(av.y, bv.y, acc11);
        }
        __syncthreads();
    }

    int m_ = m0 + 2 * ti;
    int n_ = n0 + 2 * tn;
    float b0 = 0.f, b1v = 0.f;
    if (z) { b0 = b1[n_]; b1v = b1[n_ + 1]; }
    C[(long)m_ * MLPH + n_]           = acc00 + b0;
    C[(long)m_ * MLPH + n_ + 1]       = acc01 + b1v;
    C[(long)(m_ + 1) * MLPH + n_]     = acc10 + b0;
    C[(long)(m_ + 1) * MLPH + n_ + 1] = acc11 + b1v;
}

// ---------------------------------------------------------------------------
// LSTM recurrence, intra-warp gate pairing + single barrier + double-buffered h.
// grid = 2 (dir), block = 256 (8 warps).
// Warp w, lane L: unit u = 16w + (L & 15); hi = L >> 4.
//   hi 0 -> rows (u, 250+u)      = (i, g)
//   hi 1 -> rows (125+u, 375+u)  = (f, o)   [rB clamped to 499 for pad units]
// i*g crosses lanes via shfl.xor 16; hi lanes own c and h.
// h double-buffered: step t reads sh_h[t&1], writes sh_h[(t+1)&1].
// Weights: cols 0..87 fp32 in regs (2x44 ull), cols 88..127 bf16 in smem
//   (5 x uint4 per row, cols >=125 zero). Branchless inner loop.
// ---------------------------------------------------------------------------
__global__ void __launch_bounds__(256, 1) lstm_kernel(
    const float* __restrict__ Whh_f,
    const float* __restrict__ Whh_b,
    const float* __restrict__ A,     // [2][512][500]
    float* __restrict__ H)           // [512][250]
{
    __shared__ __align__(16) uint4 sh_wb[5 * 500];   // bf16 weights, 40KB
    __shared__ __align__(16) float sh_h[256];        // double-buffered h

    const int tid = threadIdx.x;
    const int dir = blockIdx.x;
    const float* __restrict__ Whh = dir ? Whh_b : Whh_f;
    const float* __restrict__ Ad = A + dir * (T_SEQ * GATES);

    const int lane = tid & 31;
    const int w    = tid >> 5;
    const int hi   = lane >> 4;                 // 0 = (i,g), 1 = (f,o)
    const int u    = (w << 4) | (lane & 15);    // unit 0..127 (125..127 pad)
    const bool st_ok = (u < HID);
    int rA = hi ? (125 + u) : u;                // <= 252, always in bounds
    int rB = hi ? (375 + u) : (250 + u);
    if (rB > 499) rB = 499;                     // clamp pad units

    // activation constants: vB = m*tanh(m*sB) + a0  (sigmoid for hi, tanh lo)
    const float m_vb  = hi ? 0.5f : 1.0f;
    const float a0_vb = hi ? 0.5f : 0.0f;

    // stage bf16 smem weights: 5 uint4-granules of 8 cols, cols 88..127
    for (int idx = tid; idx < 5 * 500; idx += 256) {
        int q = idx / 500, rr = idx - q * 500;
        const float* wp = Whh + rr * 125;
        unsigned int uu[4];
#pragma unroll
        for (int j = 0; j < 4; ++j) {
            int c0 = 88 + 8 * q + 2 * j, c1 = c0 + 1;
            unsigned short b0 = (c0 < 125) ?
                __bfloat16_as_ushort(__float2bfloat16_rn(wp[c0])) : 0;
            unsigned short b1 = (c1 < 125) ?
                __bfloat16_as_ushort(__float2bfloat16_rn(wp[c1])) : 0;
            uu[j] = ((unsigned int)b1 << 16) | b0;
        }
        sh_wb[q * 500 + rr] = make_uint4(uu[0], uu[1], uu[2], uu[3]);
    }

    // register weights: cols 0..87 of both rows, packed ull
    ull wA[44], wB[44];
    {
        const float* fA = Whh + rA * 125;
        const float* fB = Whh + rB * 125;
#pragma unroll
        for (int p = 0; p < 44; ++p) {
            float2 tA = make_float2(fA[2 * p], fA[2 * p + 1]);
            float2 tB = make_float2(fB[2 * p], fB[2 * p + 1]);
            wA[p] = *(ull*)&tA;
            wB[p] = *(ull*)&tB;
        }
    }

    sh_h[tid] = 0.f;                 // zero both h buffers (incl. pads)
    float creg = 0.f;
    float aA = Ad[rA];
    float aB = Ad[rB];
    __syncthreads();

    for (int t = 0; t < T_SEQ; ++t) {
        const ulonglong2* h2 = (const ulonglong2*)(sh_h + ((t & 1) << 7));
        float* hw = sh_h + (((t + 1) & 1) << 7);
        const bool has_next = (t < T_SEQ - 1);
        float aA_n = has_next ? Ad[(t + 1) * GATES + rA] : 0.f;
        float aB_n = has_next ? Ad[(t + 1) * GATES + rB] : 0.f;

        ull accA0 = 0ull, accA1 = 0ull, accB0 = 0ull, accB1 = 0ull;
#pragma unroll
        for (int p = 0; p < 22; ++p) {     // cols 0..87 (registers)
            ulonglong2 hv = h2[p];
            accA0 = ffma2u(wA[2 * p],     hv.x, accA0);
            accA1 = ffma2u(wA[2 * p + 1], hv.y, accA1);
            accB0 = ffma2u(wB[2 * p],     hv.x, accB0);
            accB1 = ffma2u(wB[2 * p + 1], hv.y, accB1);
        }
#pragma unroll
        for (int q = 0; q < 5; ++q) {      // cols 88..127 (bf16 smem)
            ulonglong2 ha = h2[22 + 2 * q];
            ulonglong2 hb = h2[23 + 2 * q];
            uint4 wa = sh_wb[q * 500 + rA];
            uint4 wb = sh_wb[q * 500 + rB];
            accA0 = ffma2u(unpk(wa.x), ha.x, accA0);
            accA1 = ffma2u(unpk(wa.y), ha.y, accA1);
            accA0 = ffma2u(unpk(wa.z), hb.x, accA0);
            accA1 = ffma2u(unpk(wa.w), hb.y, accA1);
            accB0 = ffma2u(unpk(wb.x), ha.x, accB0);
            accB1 = ffma2u(unpk(wb.y), ha.y, accB1);
            accB0 = ffma2u(unpk(wb.z), hb.x, accB0);
            accB1 = ffma2u(unpk(wb.w), hb.y, accB1);
        }
        float2 fa = u2f2(fadd2u(accA0, accA1));
        float2 fb = u2f2(fadd2u(accB0, accB1));
        float sA = fa.x + fa.y + aA;
        float sB = fb.x + fb.y + aB;

        float vA = sig_mufu(sA);                          // i (lo) or f (hi)
        float vB = fmaf(m_vb, tanh_mufu(m_vb * sB), a0_vb); // g (lo) or o (hi)
        float ig  = vA * vB;                              // i*g on lo lanes
        float igx = __shfl_xor_sync(0xffffffffu, ig, 16); // hi gets i*g
        creg = vA * creg + igx;          // hi: f*c + i*g ; lo: bounded garbage
        float hv = vB * tanh_mufu(creg); // hi: o*tanh(c)
        if (hi && st_ok) {
            hw[u] = hv;
            int row = dir ? (T_SEQ - 1 - t) : t;
            H[row * DHID + dir * HID + u] = hv;
        }
        __syncthreads();
        aA = aA_n; aB = aB_n;
    }
}

// ---------------------------------------------------------------------------
// Pairwise MLP contraction:
//   out[j][i] = b2 + sum_k W2[k] * tanh(Pa[i][k] + Pb[j][k])
// ---------------------------------------------------------------------------
__global__ void __launch_bounds__(256) pair_kernel(
    const float* __restrict__ Pa,   // [512][512]
    const float* __restrict__ Pb,   // [512][512] (b1 folded in)
    const float* __restrict__ W2,   // [512]
    const float* __restrict__ b2,   // [1]
    float* __restrict__ out)        // [512][512]  row=j, col=i
{
    __shared__ float pas[64][34];
    __shared__ float pbs[64][34];
    __shared__ float w2s[64];

    const int tid = threadIdx.x;
    const int ti = tid & 15;     // i pair
    const int tj = tid >> 4;     // j pair
    const int i0 = blockIdx.x * 32;
    const int j0 = blockIdx.y * 32;

    float acc00 = 0.f, acc01 = 0.f, acc10 = 0.f, acc11 = 0.f;

    for (int kc = 0; kc < MLPH; kc += 64) {
#pragma unroll
        for (int it = 0; it < 2; ++it) {
            int idx = tid + it * 256;
            int row = idx >> 4, q = idx & 15;
            float4 va = *(const float4*)&Pa[(long)(i0 + row) * MLPH + kc + 4 * q];
            pas[4 * q + 0][row] = va.x; pas[4 * q + 1][row] = va.y;
            pas[4 * q + 2][row] = va.z; pas[4 * q + 3][row] = va.w;
            float4 vb = *(const float4*)&Pb[(long)(j0 + row) * MLPH + kc + 4 * q];
            pbs[4 * q + 0][row] = vb.x; pbs[4 * q + 1][row] = vb.y;
            pbs[4 * q + 2][row] = vb.z; pbs[4 * q + 3][row] = vb.w;
        }
        if (tid < 16) {
            float4 w = *(const float4*)&W2[kc + 4 * tid];
            w2s[4 * tid + 0] = w.x; w2s[4 * tid + 1] = w.y;
            w2s[4 * tid + 2] = w.z; w2s[4 * tid + 3] = w.w;
        }
        __syncthreads();
#pragma unroll
        for (int kk = 0; kk < 64; ++kk) {
            float w = w2s[kk];
            float2 a = *(const float2*)&pas[kk][2 * ti];
            float2 b = *(const float2*)&pbs[kk][2 * tj];
            acc00 = fmaf(w, tanh_mufu(a.x + b.x), acc00);
            acc01 = fmaf(w, tanh_mufu(a.x + b.y), acc01);
            acc10 = fmaf(w, tanh_mufu(a.y + b.x), acc10);
            acc11 = fmaf(w, tanh_mufu(a.y + b.y), acc11);
        }
        __syncthreads();
    }

    float bb = b2[0];
    int i = i0 + 2 * ti;
    int j = j0 + 2 * tj;
    *(float2*)&out[(long)j * NN + i]       = make_float2(acc00 + bb, acc10 + bb);
    *(float2*)&out[(long)(j + 1) * NN + i] = make_float2(acc01 + bb, acc11 + bb);
}

// ---------------------------------------------------------------------------
// launch
// ---------------------------------------------------------------------------
extern "C" void kernel_launch(void* const* d_in, const int* in_sizes, int n_in,
                              void* d_out, int out_size)
{
    const float* x     = (const float*)d_in[0];   // (512,1,125)
    const float* Wih_f = (const float*)d_in[1];
    const float* Whh_f = (const float*)d_in[2];
    const float* bih_f = (const float*)d_in[3];
    const float* bhh_f = (const float*)d_in[4];
    const float* Wih_b = (const float*)d_in[5];
    const float* Whh_b = (const float*)d_in[6];
    const float* bih_b = (const float*)d_in[7];
    const float* bhh_b = (const float*)d_in[8];
    const float* W1    = (const float*)d_in[9];   // (512,500)
    const float* b1    = (const float*)d_in[10];  // (512)
    const float* W2    = (const float*)d_in[11];  // (1,512)
    const float* b2    = (const float*)d_in[12];  // (1)
    float* out = (float*)d_out;

    float *pA, *pH, *pP;
    cudaGetSymbolAddress((void**)&pA, g_A);
    cudaGetSymbolAddress((void**)&pH, g_H);
    cudaGetSymbolAddress((void**)&pP, g_P);
    float* pPa = pP;
    float* pPb = pP + NN * MLPH;

    dim3 blk(256);
    // keep launch-slot layout so ncu's captured launch stays on lstm_kernel
    nudge_kernel<<<1, 32>>>();
    nudge_kernel<<<1, 32>>>();
    proj_kernel<<<dim3(16, 16, 2), blk>>>(x, Wih_f, bih_f, bhh_f,
                                          Wih_b, bih_b, bhh_b, pA);
    lstm_kernel<<<2, 256>>>(Whh_f, Whh_b, pA, pH);
    pab_kernel<<<dim3(16, 16, 2), blk>>>(pH, W1, b1, pP);
    pair_kernel<<<dim3(16, 16), blk>>>(pPa, pPb, W2, b2, out);
}